// round 15
// baseline (speedup 1.0000x reference)
#include <cuda_runtime.h>
#include <cuda_fp16.h>
#include <math.h>
#include <stdint.h>

#define NN 100000   // nodes
#define NR 4        // relations
#define NE 250000   // edges per relation
#define DD 128      // feature dim
#define NSEG (NR * NN)                 // 400000 segments
#define CAP 32                         // padded-CSR bucket capacity (P(overflow)~4e-20)

// ---------------------------------------------------------------------------
// Scratch (__device__ globals; allocation-free rule)
// g_cnt is self-resetting: gather stores 0 after reading, so the next graph
// replay starts from zeros without a memset launch.
// ---------------------------------------------------------------------------
__device__ __align__(16) __half g_xh[(size_t)NN * DD];         // fp16 x, 25.6MB
__device__ __align__(16) __half g_aggh[(size_t)NR * NN * DD];  // fp16 aggregate
__device__ __align__(16) uint32_t g_wtfh[5 * 8 * 8 * 32 * 4];  // f16 paired-frag W
__device__ int g_cnt[NSEG];                                    // per-segment degree
__device__ int g_ssrc[(size_t)NSEG * CAP];                     // padded edge buckets

// m16n8k16 F16 mma.sync (family-common PTX), fp32 accumulate
__device__ __forceinline__ void mma16(float* d, const uint32_t* a,
                                      uint32_t b0, uint32_t b1) {
    asm volatile(
        "mma.sync.aligned.m16n8k16.row.col.f32.f16.f16.f32 "
        "{%0,%1,%2,%3}, {%4,%5,%6,%7}, {%8,%9}, {%0,%1,%2,%3};"
        : "+f"(d[0]), "+f"(d[1]), "+f"(d[2]), "+f"(d[3])
        : "r"(a[0]), "r"(a[1]), "r"(a[2]), "r"(a[3]), "r"(b0), "r"(b1));
}

// ldmatrix x4 (family-common sm_75+)
__device__ __forceinline__ void ldsm4(uint32_t* r, uint32_t addr) {
    asm volatile("ldmatrix.sync.aligned.m8n8.x4.shared.b16 {%0,%1,%2,%3}, [%4];"
                 : "=r"(r[0]), "=r"(r[1]), "=r"(r[2]), "=r"(r[3]) : "r"(addr));
}

// cp.async 16B (family-common sm_80+); zfill when sz==0
__device__ __forceinline__ void cp16(uint32_t dst, const void* src, int sz) {
    asm volatile("cp.async.cg.shared.global [%0], [%1], 16, %2;"
                 :: "r"(dst), "l"(src), "r"(sz));
}
#define CP_COMMIT() asm volatile("cp.async.commit_group;" ::: "memory")
#define CP_WAIT(n)  asm volatile("cp.async.wait_group %0;" :: "n"(n) : "memory")

__device__ __forceinline__ uint32_t smem_u32(const void* p) {
    uint32_t a;
    asm("{ .reg .u64 t; cvta.to.shared.u64 t, %1; cvt.u32.u64 %0, t; }" : "=r"(a) : "l"(p));
    return a;
}

// ---------------------------------------------------------------------------
// Mega-prep (4 items/thread in the big ranges for MLP):
// [0,NPL4) place | [NPL4,NPL4+NXH4) x->fp16 | rest W pack
// ---------------------------------------------------------------------------
#define NPL4 ((NR * NE + 1023) / 1024)            // 977
#define NXH4 (NN * DD / 4 / 1024)                 // 3125 (exact)
#define NWT  ((5 * 8 * 8 * 32 * 4 + 255) / 256)   // 160
__global__ void prep_kernel(const int* __restrict__ src,
                            const int* __restrict__ dst,
                            const float* __restrict__ x,
                            const float* __restrict__ weight,
                            const float* __restrict__ loop_weight) {
    if (blockIdx.x < NPL4) {
        int base = blockIdx.x * 1024 + threadIdx.x;
#pragma unroll
        for (int i = 0; i < 4; i++) {
            int e = base + i * 256;
            if (e < NR * NE) {
                int seg = (e / NE) * NN + __ldg(&dst[e]);
                int pos = atomicAdd(&g_cnt[seg], 1);
                g_ssrc[(size_t)seg * CAP + pos] = __ldg(&src[e]);
            }
        }
    } else if (blockIdx.x < NPL4 + NXH4) {
        int base = (blockIdx.x - NPL4) * 1024 + threadIdx.x;
#pragma unroll
        for (int i = 0; i < 4; i++) {
            int idx = base + i * 256;
            float4 v = __ldg(reinterpret_cast<const float4*>(x) + idx);
            union { __half2 h[2]; uint2 u; } p;
            p.h[0] = __floats2half2_rn(v.x, v.y);
            p.h[1] = __floats2half2_rn(v.z, v.w);
            reinterpret_cast<uint2*>(g_xh)[idx] = p.u;
        }
    } else {
        int idx = (blockIdx.x - NPL4 - NXH4) * 256 + threadIdx.x;
        if (idx >= 5 * 8 * 8 * 32 * 4) return;
        int c = idx & 3;
        int l = (idx >> 2) & 31;
        int q = (idx >> 7) & 7;
        int t = (idx >> 10) & 7;
        int s = idx >> 13;
        int j = 2 * q + (c >> 1);
        int r = c & 1;
        int n = j * 8 + (l >> 2);
        int k = t * 16 + 2 * (l & 3) + 8 * r;
        const float* W = (s < 4) ? weight + (size_t)s * DD * DD : loop_weight;
        union { __half2 h; uint32_t u; } p;
        p.h = __floats2half2_rn(W[(size_t)k * DD + n], W[(size_t)(k + 1) * DD + n]);
        g_wtfh[idx] = p.u;
    }
}

// ---------------------------------------------------------------------------
// Gather: one warp per (rel,node). Broadcast LDG degree (parallel with int4
// bucket-head load), up to 4 independent x-row loads; lane0 resets counter.
// ---------------------------------------------------------------------------
__global__ void gather_kernel() {
    unsigned wid  = (blockIdx.x * blockDim.x + threadIdx.x) >> 5;
    unsigned lane = threadIdx.x & 31;
    if (wid >= (unsigned)NSEG) return;
    const int* bucket = g_ssrc + (size_t)wid * CAP;
    int deg = g_cnt[wid];                          // broadcast L2 load
    int4 bb = __ldg(reinterpret_cast<const int4*>(bucket));   // independent
    if (lane == 0) g_cnt[wid] = 0;                 // self-reset (one owner warp)

    const uint2* xh2 = reinterpret_cast<const uint2*>(g_xh);
    float a0 = 0.f, a1 = 0.f, a2 = 0.f, a3 = 0.f;

    if (deg > 0) {
        uint2 v = xh2[(size_t)bb.x * 32 + lane];
        float2 p0 = __half22float2(*reinterpret_cast<__half2*>(&v.x));
        float2 p1 = __half22float2(*reinterpret_cast<__half2*>(&v.y));
        a0 += p0.x; a1 += p0.y; a2 += p1.x; a3 += p1.y;
    }
    if (deg > 1) {
        uint2 v = xh2[(size_t)bb.y * 32 + lane];
        float2 p0 = __half22float2(*reinterpret_cast<__half2*>(&v.x));
        float2 p1 = __half22float2(*reinterpret_cast<__half2*>(&v.y));
        a0 += p0.x; a1 += p0.y; a2 += p1.x; a3 += p1.y;
    }
    if (deg > 2) {
        uint2 v = xh2[(size_t)bb.z * 32 + lane];
        float2 p0 = __half22float2(*reinterpret_cast<__half2*>(&v.x));
        float2 p1 = __half22float2(*reinterpret_cast<__half2*>(&v.y));
        a0 += p0.x; a1 += p0.y; a2 += p1.x; a3 += p1.y;
    }
    if (deg > 3) {
        uint2 v = xh2[(size_t)bb.w * 32 + lane];
        float2 p0 = __half22float2(*reinterpret_cast<__half2*>(&v.x));
        float2 p1 = __half22float2(*reinterpret_cast<__half2*>(&v.y));
        a0 += p0.x; a1 += p0.y; a2 += p1.x; a3 += p1.y;
    }
    for (int e = 4; e < deg; e++) {
        uint2 v = xh2[(size_t)__ldg(&bucket[e]) * 32 + lane];
        float2 p0 = __half22float2(*reinterpret_cast<__half2*>(&v.x));
        float2 p1 = __half22float2(*reinterpret_cast<__half2*>(&v.y));
        a0 += p0.x; a1 += p0.y; a2 += p1.x; a3 += p1.y;
    }
    float rd = 1.0f / fmaxf((float)deg, 1.0f);
    union { __half2 h[2]; uint2 u; } p;
    p.h[0] = __floats2half2_rn(a0 * rd, a1 * rd);
    p.h[1] = __floats2half2_rn(a2 * rd, a3 * rd);
    __stcs(reinterpret_cast<uint2*>(g_aggh) + (size_t)wid * 32 + lane, p.u);
}

// ---------------------------------------------------------------------------
// F16 mma.sync fused 5-way GEMM + epilogue.
// Tile M=64, N=128, K=128/stage. Block 256 = 2 M-warps x 4 N-warps.
// BOTH A and W double-buffered: A(s+1)/W(s+1) committed at stage-s top, so
// the inter-stage critical path is epilogue+sync only. 103KB smem, 2 CTA/SM.
// ---------------------------------------------------------------------------
#define MT 64
#define LDAH 136                                   // padded A row (halves)
#define A_BYTES (MT * LDAH * 2)                    // 17408
#define W_BYTES 32768
#define OFF_BIAS 0
#define OFF_A0   2560
#define OFF_A1   (OFF_A0 + A_BYTES)                // 19968
#define OFF_W0   (OFF_A1 + A_BYTES)                // 37376
#define OFF_W1   (OFF_W0 + W_BYTES)                // 70144
#define SMEM_TOTAL (OFF_W1 + W_BYTES)              // 102912

__global__ __launch_bounds__(256, 2)
void gemm_mma(const float* __restrict__ conv_bias,
              const float* __restrict__ node_bias,
              float* __restrict__ out) {
    extern __shared__ char smem[];
    const uint32_t sb = smem_u32(smem);
    float* sbias = reinterpret_cast<float*>(smem + OFF_BIAS);

    const int tid   = threadIdx.x;
    const int lane  = tid & 31;
    const int warp  = tid >> 5;
    const int mwarp = warp & 1;        // 0..1 (M, 32 rows each)
    const int nwarp = warp >> 1;       // 0..3 (N, 32 cols each)
    const int mbase = blockIdx.x * MT;
    const int lr    = lane >> 2;       // 0..7
    const int lc    = lane & 3;        // 0..3

    for (int i = tid; i < 512; i += 256) sbias[i] = conv_bias[i];
    for (int i = tid; i < 128; i += 256) sbias[512 + i] = node_bias[i];

    const int arow = tid >> 4;         // 0..15
    const int ac8  = tid & 15;

    auto copy_A = [&](int s, uint32_t abuf) {
        const uint4* Ag = (s < 4)
            ? reinterpret_cast<const uint4*>(g_aggh) + (size_t)s * NN * 16
            : reinterpret_cast<const uint4*>(g_xh);
#pragma unroll
        for (int it = 0; it < 4; it++) {
            int row = arow + it * 16;
            int gr = mbase + row;
            cp16(abuf + row * (LDAH * 2) + ac8 * 16,
                 Ag + (size_t)gr * 16 + ac8, gr < NN ? 16 : 0);
        }
        CP_COMMIT();
    };
    auto copy_W = [&](int s, uint32_t wbuf) {
        const uint4* Wg = reinterpret_cast<const uint4*>(g_wtfh) + (size_t)s * 2048;
#pragma unroll
        for (int it = 0; it < 8; it++)
            cp16(wbuf + (tid + it * 256) * 16, Wg + tid + it * 256, 16);
        CP_COMMIT();
    };

    float hsum[2][4][4];
#pragma unroll
    for (int mi = 0; mi < 2; mi++)
#pragma unroll
        for (int j = 0; j < 4; j++)
#pragma unroll
            for (int r = 0; r < 4; r++) hsum[mi][j][r] = 0.f;

    float acc[2][4][4];

    const int lm_row = lane & 15;
    const int lm_col = (lane >> 4) * 16;

    // prologue: stage-0 buffers (groups: A0, W0)
    copy_A(0, sb + OFF_A0);
    copy_W(0, sb + OFF_W0);

    for (int s = 0; s < 5; s++) {
        const uint32_t abase = sb + ((s & 1) ? OFF_A1 : OFF_A0);
        const uint4* Bw = reinterpret_cast<const uint4*>(
            smem + ((s & 1) ? OFF_W1 : OFF_W0));

        if (s + 1 < 5) {
            // prefetch next stage into the other buffers (groups: A(s+1), W(s+1))
            copy_A(s + 1, sb + ((s & 1) ? OFF_A0 : OFF_A1));
            copy_W(s + 1, sb + ((s & 1) ? OFF_W0 : OFF_W1));
            CP_WAIT(2);     // A(s), W(s) landed; next-stage pair in flight
        } else {
            CP_WAIT(0);
        }
        __syncthreads();

#pragma unroll
        for (int mi = 0; mi < 2; mi++)
#pragma unroll
            for (int j = 0; j < 4; j++)
#pragma unroll
                for (int r = 0; r < 4; r++) acc[mi][j][r] = 0.f;

        // --- mainloop: 8 k-steps of K=16 ---
#pragma unroll
        for (int t = 0; t < 8; t++) {
            uint32_t a[2][4];
#pragma unroll
            for (int mi = 0; mi < 2; mi++) {
                int rr = mwarp * 32 + mi * 16 + lm_row;
                ldsm4(a[mi], abase + rr * (LDAH * 2) + t * 32 + lm_col);
            }
            uint4 b[2];
#pragma unroll
            for (int p = 0; p < 2; p++)
                b[p] = Bw[(t * 8 + nwarp * 2 + p) * 32 + lane];
#pragma unroll
            for (int mi = 0; mi < 2; mi++)
#pragma unroll
                for (int p = 0; p < 2; p++) {
                    mma16(acc[mi][2 * p],     a[mi], b[p].x, b[p].y);
                    mma16(acc[mi][2 * p + 1], a[mi], b[p].z, b[p].w);
                }
        }

        if (s < 4) {
            // --- per-relation epilogue: relu(acc + bias) accumulated ---
#pragma unroll
            for (int mi = 0; mi < 2; mi++)
#pragma unroll
                for (int j = 0; j < 4; j++) {
                    int col = nwarp * 32 + j * 8 + lc * 2;
                    float b0 = sbias[s * 128 + col];
                    float b1 = sbias[s * 128 + col + 1];
                    hsum[mi][j][0] += fmaxf(acc[mi][j][0] + b0, 0.f);
                    hsum[mi][j][1] += fmaxf(acc[mi][j][1] + b1, 0.f);
                    hsum[mi][j][2] += fmaxf(acc[mi][j][2] + b0, 0.f);
                    hsum[mi][j][3] += fmaxf(acc[mi][j][3] + b1, 0.f);
                }
            __syncthreads();   // stage-s buffer reads done before s+2 prefetch
        } else {
            // --- final epilogue: mean, SiLU, + self-loop + node bias, ReLU ---
#pragma unroll
            for (int mi = 0; mi < 2; mi++) {
                int row = mbase + mwarp * 32 + mi * 16 + lr;
#pragma unroll
                for (int j = 0; j < 4; j++) {
                    int col = nwarp * 32 + j * 8 + lc * 2;
                    float nb0 = sbias[512 + col];
                    float nb1 = sbias[512 + col + 1];
                    float h, o0, o1;
                    if (row < NN) {
                        h = hsum[mi][j][0] * 0.25f;
                        h = h / (1.f + __expf(-h));
                        o0 = fmaxf(h + acc[mi][j][0] + nb0, 0.f);
                        h = hsum[mi][j][1] * 0.25f;
                        h = h / (1.f + __expf(-h));
                        o1 = fmaxf(h + acc[mi][j][1] + nb1, 0.f);
                        __stcs(reinterpret_cast<float2*>(out + (size_t)row * DD + col),
                               make_float2(o0, o1));
                    }
                    if (row + 8 < NN) {
                        h = hsum[mi][j][2] * 0.25f;
                        h = h / (1.f + __expf(-h));
                        o0 = fmaxf(h + acc[mi][j][2] + nb0, 0.f);
                        h = hsum[mi][j][3] * 0.25f;
                        h = h / (1.f + __expf(-h));
                        o1 = fmaxf(h + acc[mi][j][3] + nb1, 0.f);
                        __stcs(reinterpret_cast<float2*>(out + (size_t)(row + 8) * DD + col),
                               make_float2(o0, o1));
                    }
                }
            }
        }
    }
}

// ---------------------------------------------------------------------------
extern "C" void kernel_launch(void* const* d_in, const int* in_sizes, int n_in,
                              void* d_out, int out_size) {
    const float* x           = (const float*)d_in[0];
    const float* weight      = (const float*)d_in[1];
    const float* conv_bias   = (const float*)d_in[2];
    const float* loop_weight = (const float*)d_in[3];
    const float* node_bias   = (const float*)d_in[4];
    const int*   src         = (const int*)d_in[5];
    const int*   dst         = (const int*)d_in[6];
    float* out = (float*)d_out;

    // mega-prep: padded-CSR place + x->fp16 + W fragment pack (one launch).
    // g_cnt starts zeroed (initial state or reset by previous gather run).
    prep_kernel<<<NPL4 + NXH4 + NWT, 256>>>(src, dst, x, weight, loop_weight);

    // Gather (broadcast-LDG degree, MLP x-loads, self-resetting counters)
    gather_kernel<<<(NSEG * 32 + 255) / 256, 256>>>();

    // Fused tensor-core GEMM + epilogue (A+W double-buffered, 2 CTAs/SM)
    cudaFuncSetAttribute(gemm_mma, cudaFuncAttributeMaxDynamicSharedMemorySize,
                         SMEM_TOTAL);
    gemm_mma<<<(NN + MT - 1) / MT, 256, SMEM_TOTAL>>>(conv_bias, node_bias, out);
}

// round 16
// speedup vs baseline: 1.6785x; 1.6785x over previous
#include <cuda_runtime.h>
#include <cuda_fp16.h>
#include <math.h>
#include <stdint.h>

#define NN 100000   // nodes
#define NR 4        // relations
#define NE 250000   // edges per relation
#define DD 128      // feature dim
#define NSEG (NR * NN)                 // 400000 segments
#define CAP 32                         // padded-CSR bucket capacity (P(overflow)~4e-20)

// ---------------------------------------------------------------------------
// Scratch (__device__ globals; allocation-free rule)
// g_cnt is self-resetting: gather atomically exchanges each counter to 0,
// so the next graph replay starts from zeros without a memset launch.
// ---------------------------------------------------------------------------
__device__ __align__(16) __half g_xh[(size_t)NN * DD];         // fp16 x, 25.6MB
__device__ __align__(16) __half g_aggh[(size_t)NR * NN * DD];  // fp16 aggregate
__device__ __align__(16) uint32_t g_wtfh[5 * 8 * 8 * 32 * 4];  // f16 paired-frag W
__device__ int g_cnt[NSEG];                                    // per-segment degree
__device__ int g_ssrc[(size_t)NSEG * CAP];                     // padded edge buckets

// m16n8k16 F16 mma.sync (family-common PTX), fp32 accumulate
__device__ __forceinline__ void mma16(float* d, const uint32_t* a,
                                      uint32_t b0, uint32_t b1) {
    asm volatile(
        "mma.sync.aligned.m16n8k16.row.col.f32.f16.f16.f32 "
        "{%0,%1,%2,%3}, {%4,%5,%6,%7}, {%8,%9}, {%0,%1,%2,%3};"
        : "+f"(d[0]), "+f"(d[1]), "+f"(d[2]), "+f"(d[3])
        : "r"(a[0]), "r"(a[1]), "r"(a[2]), "r"(a[3]), "r"(b0), "r"(b1));
}

// ldmatrix x4 (family-common sm_75+)
__device__ __forceinline__ void ldsm4(uint32_t* r, uint32_t addr) {
    asm volatile("ldmatrix.sync.aligned.m8n8.x4.shared.b16 {%0,%1,%2,%3}, [%4];"
                 : "=r"(r[0]), "=r"(r[1]), "=r"(r[2]), "=r"(r[3]) : "r"(addr));
}

// cp.async 16B (family-common sm_80+); zfill when sz==0
__device__ __forceinline__ void cp16(uint32_t dst, const void* src, int sz) {
    asm volatile("cp.async.cg.shared.global [%0], [%1], 16, %2;"
                 :: "r"(dst), "l"(src), "r"(sz));
}
#define CP_COMMIT() asm volatile("cp.async.commit_group;" ::: "memory")
#define CP_WAIT(n)  asm volatile("cp.async.wait_group %0;" :: "n"(n) : "memory")

__device__ __forceinline__ uint32_t smem_u32(const void* p) {
    uint32_t a;
    asm("{ .reg .u64 t; cvta.to.shared.u64 t, %1; cvt.u32.u64 %0, t; }" : "=r"(a) : "l"(p));
    return a;
}

// ---------------------------------------------------------------------------
// Mega-prep (4 items/thread in the big ranges for MLP):
// [0,NPL4) place | [NPL4,NPL4+NXH4) x->fp16 | rest W pack
// ---------------------------------------------------------------------------
#define NPL4 ((NR * NE + 1023) / 1024)            // 977
#define NXH4 (NN * DD / 4 / 1024)                 // 3125 (exact)
#define NWT  ((5 * 8 * 8 * 32 * 4 + 255) / 256)   // 160
__global__ void prep_kernel(const int* __restrict__ src,
                            const int* __restrict__ dst,
                            const float* __restrict__ x,
                            const float* __restrict__ weight,
                            const float* __restrict__ loop_weight) {
    if (blockIdx.x < NPL4) {
        int base = blockIdx.x * 1024 + threadIdx.x;
#pragma unroll
        for (int i = 0; i < 4; i++) {
            int e = base + i * 256;
            if (e < NR * NE) {
                int seg = (e / NE) * NN + __ldg(&dst[e]);
                int pos = atomicAdd(&g_cnt[seg], 1);
                g_ssrc[(size_t)seg * CAP + pos] = __ldg(&src[e]);
            }
        }
    } else if (blockIdx.x < NPL4 + NXH4) {
        int base = (blockIdx.x - NPL4) * 1024 + threadIdx.x;
#pragma unroll
        for (int i = 0; i < 4; i++) {
            int idx = base + i * 256;
            float4 v = __ldg(reinterpret_cast<const float4*>(x) + idx);
            union { __half2 h[2]; uint2 u; } p;
            p.h[0] = __floats2half2_rn(v.x, v.y);
            p.h[1] = __floats2half2_rn(v.z, v.w);
            reinterpret_cast<uint2*>(g_xh)[idx] = p.u;
        }
    } else {
        int idx = (blockIdx.x - NPL4 - NXH4) * 256 + threadIdx.x;
        if (idx >= 5 * 8 * 8 * 32 * 4) return;
        int c = idx & 3;
        int l = (idx >> 2) & 31;
        int q = (idx >> 7) & 7;
        int t = (idx >> 10) & 7;
        int s = idx >> 13;
        int j = 2 * q + (c >> 1);
        int r = c & 1;
        int n = j * 8 + (l >> 2);
        int k = t * 16 + 2 * (l & 3) + 8 * r;
        const float* W = (s < 4) ? weight + (size_t)s * DD * DD : loop_weight;
        union { __half2 h; uint32_t u; } p;
        p.h = __floats2half2_rn(W[(size_t)k * DD + n], W[(size_t)(k + 1) * DD + n]);
        g_wtfh[idx] = p.u;
    }
}

// ---------------------------------------------------------------------------
// Gather: one warp per (rel,node). int4 bucket head -> up to 4 independent
// x-row loads (MLP); fp32 accumulate; streaming fp16 store.
// Self-resets g_cnt via atomicExch (removes the memset launch).
// ---------------------------------------------------------------------------
__global__ void gather_kernel() {
    unsigned wid  = (blockIdx.x * blockDim.x + threadIdx.x) >> 5;
    unsigned lane = threadIdx.x & 31;
    if (wid >= (unsigned)NSEG) return;
    const int* bucket = g_ssrc + (size_t)wid * CAP;
    int deg = 0;
    if (lane == 0) deg = atomicExch(&g_cnt[wid], 0);
    deg = __shfl_sync(0xffffffffu, deg, 0);

    const uint2* xh2 = reinterpret_cast<const uint2*>(g_xh);
    float a0 = 0.f, a1 = 0.f, a2 = 0.f, a3 = 0.f;

    int4 bb = __ldg(reinterpret_cast<const int4*>(bucket));   // first 4 srcs
    if (deg > 0) {
        uint2 v = xh2[(size_t)bb.x * 32 + lane];
        float2 p0 = __half22float2(*reinterpret_cast<__half2*>(&v.x));
        float2 p1 = __half22float2(*reinterpret_cast<__half2*>(&v.y));
        a0 += p0.x; a1 += p0.y; a2 += p1.x; a3 += p1.y;
    }
    if (deg > 1) {
        uint2 v = xh2[(size_t)bb.y * 32 + lane];
        float2 p0 = __half22float2(*reinterpret_cast<__half2*>(&v.x));
        float2 p1 = __half22float2(*reinterpret_cast<__half2*>(&v.y));
        a0 += p0.x; a1 += p0.y; a2 += p1.x; a3 += p1.y;
    }
    if (deg > 2) {
        uint2 v = xh2[(size_t)bb.z * 32 + lane];
        float2 p0 = __half22float2(*reinterpret_cast<__half2*>(&v.x));
        float2 p1 = __half22float2(*reinterpret_cast<__half2*>(&v.y));
        a0 += p0.x; a1 += p0.y; a2 += p1.x; a3 += p1.y;
    }
    if (deg > 3) {
        uint2 v = xh2[(size_t)bb.w * 32 + lane];
        float2 p0 = __half22float2(*reinterpret_cast<__half2*>(&v.x));
        float2 p1 = __half22float2(*reinterpret_cast<__half2*>(&v.y));
        a0 += p0.x; a1 += p0.y; a2 += p1.x; a3 += p1.y;
    }
    for (int e = 4; e < deg; e++) {
        uint2 v = xh2[(size_t)__ldg(&bucket[e]) * 32 + lane];
        float2 p0 = __half22float2(*reinterpret_cast<__half2*>(&v.x));
        float2 p1 = __half22float2(*reinterpret_cast<__half2*>(&v.y));
        a0 += p0.x; a1 += p0.y; a2 += p1.x; a3 += p1.y;
    }
    float rd = 1.0f / fmaxf((float)deg, 1.0f);
    union { __half2 h[2]; uint2 u; } p;
    p.h[0] = __floats2half2_rn(a0 * rd, a1 * rd);
    p.h[1] = __floats2half2_rn(a2 * rd, a3 * rd);
    __stcs(reinterpret_cast<uint2*>(g_aggh) + (size_t)wid * 32 + lane, p.u);
}

// ---------------------------------------------------------------------------
// F16 mma.sync fused 5-way GEMM + epilogue (R14 skeleton; single-buffer W).
// Tile M=64, N=128, K=128/stage. Block 256 = 2 M-warps x 4 N-warps.
// Change vs R14: copy_W(s+1) is issued BEFORE the per-relation epilogue so
// the W refill overlaps the register-only hsum work.
// ---------------------------------------------------------------------------
#define MT 64
#define LDAH 136                                   // padded A row (halves)
#define A_BYTES (MT * LDAH * 2)                    // 17408
#define W_BYTES 32768
#define OFF_BIAS 0
#define OFF_A0   2560
#define OFF_A1   (OFF_A0 + A_BYTES)                // 19968
#define OFF_W    (OFF_A1 + A_BYTES)                // 37376
#define SMEM_TOTAL (OFF_W + W_BYTES)               // 70144

__global__ __launch_bounds__(256, 2)
void gemm_mma(const float* __restrict__ conv_bias,
              const float* __restrict__ node_bias,
              float* __restrict__ out) {
    extern __shared__ char smem[];
    const uint32_t sb = smem_u32(smem);
    float* sbias = reinterpret_cast<float*>(smem + OFF_BIAS);
    const uint4* Bw = reinterpret_cast<const uint4*>(smem + OFF_W);

    const int tid   = threadIdx.x;
    const int lane  = tid & 31;
    const int warp  = tid >> 5;
    const int mwarp = warp & 1;        // 0..1 (M, 32 rows each)
    const int nwarp = warp >> 1;       // 0..3 (N, 32 cols each)
    const int mbase = blockIdx.x * MT;
    const int lr    = lane >> 2;       // 0..7
    const int lc    = lane & 3;        // 0..3

    for (int i = tid; i < 512; i += 256) sbias[i] = conv_bias[i];
    for (int i = tid; i < 128; i += 256) sbias[512 + i] = node_bias[i];

    const int arow = tid >> 4;         // 0..15
    const int ac8  = tid & 15;

    auto copy_A = [&](int s, uint32_t abuf) {
        const uint4* Ag = (s < 4)
            ? reinterpret_cast<const uint4*>(g_aggh) + (size_t)s * NN * 16
            : reinterpret_cast<const uint4*>(g_xh);
#pragma unroll
        for (int it = 0; it < 4; it++) {
            int row = arow + it * 16;
            int gr = mbase + row;
            cp16(abuf + row * (LDAH * 2) + ac8 * 16,
                 Ag + (size_t)gr * 16 + ac8, gr < NN ? 16 : 0);
        }
        CP_COMMIT();
    };
    auto copy_W = [&](int s) {
        const uint4* Wg = reinterpret_cast<const uint4*>(g_wtfh) + (size_t)s * 2048;
#pragma unroll
        for (int it = 0; it < 8; it++)
            cp16(sb + OFF_W + (tid + it * 256) * 16, Wg + tid + it * 256, 16);
        CP_COMMIT();
    };

    float hsum[2][4][4];
#pragma unroll
    for (int mi = 0; mi < 2; mi++)
#pragma unroll
        for (int j = 0; j < 4; j++)
#pragma unroll
            for (int r = 0; r < 4; r++) hsum[mi][j][r] = 0.f;

    float acc[2][4][4];

    const int lm_row = lane & 15;
    const int lm_col = (lane >> 4) * 16;

    copy_A(0, sb + OFF_A0);
    copy_W(0);

    for (int s = 0; s < 5; s++) {
        const uint32_t abase = sb + ((s & 1) ? OFF_A1 : OFF_A0);

        if (s + 1 < 5) {
            copy_A(s + 1, (s & 1) ? (sb + OFF_A0) : (sb + OFF_A1));
            CP_WAIT(1);     // A(s)+W(s) landed; A(s+1) in flight
        } else {
            CP_WAIT(0);
        }
        __syncthreads();

#pragma unroll
        for (int mi = 0; mi < 2; mi++)
#pragma unroll
            for (int j = 0; j < 4; j++)
#pragma unroll
                for (int r = 0; r < 4; r++) acc[mi][j][r] = 0.f;

        // --- mainloop: 8 k-steps of K=16 ---
#pragma unroll
        for (int t = 0; t < 8; t++) {
            uint32_t a[2][4];
#pragma unroll
            for (int mi = 0; mi < 2; mi++) {
                int rr = mwarp * 32 + mi * 16 + lm_row;
                ldsm4(a[mi], abase + rr * (LDAH * 2) + t * 32 + lm_col);
            }
            uint4 b[2];
#pragma unroll
            for (int p = 0; p < 2; p++)
                b[p] = Bw[(t * 8 + nwarp * 2 + p) * 32 + lane];
#pragma unroll
            for (int mi = 0; mi < 2; mi++)
#pragma unroll
                for (int p = 0; p < 2; p++) {
                    mma16(acc[mi][2 * p],     a[mi], b[p].x, b[p].y);
                    mma16(acc[mi][2 * p + 1], a[mi], b[p].z, b[p].w);
                }
        }

        if (s < 4) {
            __syncthreads();            // all warps done reading W(s) and A(s)
            copy_W(s + 1);              // start refill NOW; epilogue hides it
            // --- per-relation epilogue: relu(acc + bias) accumulated ---
#pragma unroll
            for (int mi = 0; mi < 2; mi++)
#pragma unroll
                for (int j = 0; j < 4; j++) {
                    int col = nwarp * 32 + j * 8 + lc * 2;
                    float b0 = sbias[s * 128 + col];
                    float b1 = sbias[s * 128 + col + 1];
                    hsum[mi][j][0] += fmaxf(acc[mi][j][0] + b0, 0.f);
                    hsum[mi][j][1] += fmaxf(acc[mi][j][1] + b1, 0.f);
                    hsum[mi][j][2] += fmaxf(acc[mi][j][2] + b0, 0.f);
                    hsum[mi][j][3] += fmaxf(acc[mi][j][3] + b1, 0.f);
                }
        } else {
            // --- final epilogue: mean, SiLU, + self-loop + node bias, ReLU ---
#pragma unroll
            for (int mi = 0; mi < 2; mi++) {
                int row = mbase + mwarp * 32 + mi * 16 + lr;
#pragma unroll
                for (int j = 0; j < 4; j++) {
                    int col = nwarp * 32 + j * 8 + lc * 2;
                    float nb0 = sbias[512 + col];
                    float nb1 = sbias[512 + col + 1];
                    float h, o0, o1;
                    if (row < NN) {
                        h = hsum[mi][j][0] * 0.25f;
                        h = h / (1.f + __expf(-h));
                        o0 = fmaxf(h + acc[mi][j][0] + nb0, 0.f);
                        h = hsum[mi][j][1] * 0.25f;
                        h = h / (1.f + __expf(-h));
                        o1 = fmaxf(h + acc[mi][j][1] + nb1, 0.f);
                        __stcs(reinterpret_cast<float2*>(out + (size_t)row * DD + col),
                               make_float2(o0, o1));
                    }
                    if (row + 8 < NN) {
                        h = hsum[mi][j][2] * 0.25f;
                        h = h / (1.f + __expf(-h));
                        o0 = fmaxf(h + acc[mi][j][2] + nb0, 0.f);
                        h = hsum[mi][j][3] * 0.25f;
                        h = h / (1.f + __expf(-h));
                        o1 = fmaxf(h + acc[mi][j][3] + nb1, 0.f);
                        __stcs(reinterpret_cast<float2*>(out + (size_t)(row + 8) * DD + col),
                               make_float2(o0, o1));
                    }
                }
            }
        }
    }
}

// ---------------------------------------------------------------------------
extern "C" void kernel_launch(void* const* d_in, const int* in_sizes, int n_in,
                              void* d_out, int out_size) {
    const float* x           = (const float*)d_in[0];
    const float* weight      = (const float*)d_in[1];
    const float* conv_bias   = (const float*)d_in[2];
    const float* loop_weight = (const float*)d_in[3];
    const float* node_bias   = (const float*)d_in[4];
    const int*   src         = (const int*)d_in[5];
    const int*   dst         = (const int*)d_in[6];
    float* out = (float*)d_out;

    // mega-prep: padded-CSR place + x->fp16 + W fragment pack (one launch).
    // g_cnt starts zeroed (initial state or reset by previous gather run).
    prep_kernel<<<NPL4 + NXH4 + NWT, 256>>>(src, dst, x, weight, loop_weight);

    // Gather (int4 bucket head, MLP x-loads, self-resetting counters)
    gather_kernel<<<(NSEG * 32 + 255) / 256, 256>>>();

    // Fused tensor-core GEMM + epilogue (M=64 tiles, ldmatrix, 2 CTAs/SM)
    cudaFuncSetAttribute(gemm_mma, cudaFuncAttributeMaxDynamicSharedMemorySize,
                         SMEM_TOTAL);
    gemm_mma<<<(NN + MT - 1) / MT, 256, SMEM_TOTAL>>>(conv_bias, node_bias, out);
}